// round 1
// baseline (speedup 1.0000x reference)
#include <cuda_runtime.h>
#include <cuda_bf16.h>

// Problem constants (from reference setup_inputs):
//   char_feats: [L=512, B=256, D=256] float32  (time-major)
//   word_ids:   [B=256, L=512] int32 (per-row non-decreasing, dense 0..n-1, < 128)
//   attention_mask: [B, L] int32
// Output: word_feats [W=128, B, D] f32, then masks [W, B] as f32 (if out_size
// includes them).
#define LSEQ 512
#define NW   128
#define BATCH 256
#define DDIM  256

// Scratch: word-start boundaries per batch (start[W] slot = end sentinel),
// valid-window hi, and word count. __device__ globals per allocation rules.
__device__ int g_start[BATCH * (NW + 1)];
__device__ int g_validhi[BATCH];
__device__ int g_wordnum[BATCH];

// One block per batch row, 512 threads (= L).
__global__ void boundary_kernel(const int* __restrict__ word_ids,
                                const int* __restrict__ amask) {
    int b = blockIdx.x;
    int t = threadIdx.x;

    __shared__ int ids[LSEQ];
    __shared__ int red[LSEQ];

    int id = word_ids[b * LSEQ + t];
    id = id < 0 ? 0 : (id > NW - 1 ? NW - 1 : id);  // defensive clamp
    ids[t] = id;
    red[t] = amask[b * LSEQ + t];
    __syncthreads();

    // Reduce attention mask -> char count
    #pragma unroll
    for (int s = LSEQ / 2; s > 0; s >>= 1) {
        if (t < s) red[t] += red[t + s];
        __syncthreads();
    }

    // Init all starts to L (sentinel / empty words)
    if (t <= NW) g_start[b * (NW + 1) + t] = LSEQ;
    __syncthreads();

    // Mark boundaries. word_ids are dense+sorted so each word's first
    // occurrence defines its start; end = start of next word.
    if (t == 0) {
        g_start[b * (NW + 1) + ids[0]] = 0;
        int char_nums = red[0] - 2;            // drop [CLS]/[SEP]
        g_validhi[b] = 1 + char_nums;          // valid chars: l in [1, 1+char_nums)
        g_wordnum[b] = ids[LSEQ - 1] + 1;      // sorted -> max is last element
    } else if (ids[t] != ids[t - 1]) {
        g_start[b * (NW + 1) + ids[t]] = t;
    }
}

// One block per (word, batch). 64 threads x float4 = 256 floats = D.
__global__ void pool_kernel(const float* __restrict__ cf,
                            float* __restrict__ out,
                            float* __restrict__ mask_out) {
    int w = blockIdx.x;
    int b = blockIdx.y;
    int t = threadIdx.x;  // 0..63

    int base = b * (NW + 1) + w;
    int s = g_start[base];
    int e = g_start[base + 1];
    int hi = g_validhi[b];

    // Intersect word range with valid window
    s = s > 1 ? s : 1;
    e = e < hi ? e : hi;
    int cnt = e - s;

    const int stride4 = BATCH * DDIM / 4;  // float4 stride per l
    const float4* p = reinterpret_cast<const float4*>(cf)
                    + (long long)s * stride4 + b * (DDIM / 4) + t;

    float4 acc = make_float4(0.f, 0.f, 0.f, 0.f);
    for (int l = s; l < e; ++l) {
        float4 v = __ldg(p);
        acc.x += v.x; acc.y += v.y; acc.z += v.z; acc.w += v.w;
        p += stride4;
    }

    // mean = sum / max(count, 1); empty word -> 0 (acc already 0)
    float c = (float)(cnt > 0 ? cnt : 1);
    acc.x /= c; acc.y /= c; acc.z /= c; acc.w /= c;

    float4* o = reinterpret_cast<float4*>(out)
              + (long long)(w * BATCH + b) * (DDIM / 4) + t;
    *o = acc;

    if (t == 0 && mask_out != nullptr) {
        mask_out[w * BATCH + b] = (w < g_wordnum[b]) ? 1.0f : 0.0f;
    }
}

extern "C" void kernel_launch(void* const* d_in, const int* in_sizes, int n_in,
                              void* d_out, int out_size) {
    const float* char_feats = (const float*)d_in[0];
    const int*   word_ids   = (const int*)d_in[1];
    const int*   amask      = (const int*)d_in[2];
    float* out = (float*)d_out;

    // masks appended after word_feats if the harness expects them
    const int feats_elems = NW * BATCH * DDIM;
    float* mask_out = (out_size > feats_elems) ? (out + feats_elems) : nullptr;

    boundary_kernel<<<BATCH, LSEQ>>>(word_ids, amask);
    pool_kernel<<<dim3(NW, BATCH), 64>>>(char_feats, out, mask_out);
}